// round 17
// baseline (speedup 1.0000x reference)
#include <cuda_runtime.h>
#include <cstdint>

#define NN 8192
#define KF 256
#define CT 32
#define EPSF 1e-10f

// ---------------- scratch ----------------
__device__ float2 g_T[(size_t)KF * NN];     // [k][node] interleaved (c,s), 16 MB
__device__ uint8_t g_kk8[(size_t)NN * CT];  // CSR k indices (ascending)
__device__ float2 g_csr[(size_t)NN * CT];   // CSR (c,s) values
__device__ uint8_t g_j0[NN];                // #selected k < 128 (stage split)
__device__ float g_sqf[NN];                 // f32 sq (ref-order emulated)
__device__ float g_den[NN];                 // f32 rowsum + eps (ref-order emulated)
__device__ float g_rcp[NN];                 // fl32(1/den) for Markstein division
__device__ double g_psum;
__device__ unsigned long long g_pcnt;
__device__ float g_tau;

__global__ void zero_stats_kernel() { g_psum = 0.0; g_pcnt = 0ull; }

// Markstein division (bit-equal to __fdiv_rn except ~2^-24 boundary cases,
// applied consistently in stats + thresh).
__device__ __forceinline__ float mdiv(float v, float den, float y) {
    const float q0 = __fmul_rn(v, y);
    const float r  = __fmaf_rn(-q0, den, v);
    return __fmaf_rn(r, y, q0);
}

// ---------------- build: top-32, fp32 trig, interleaved layouts ----------------
__global__ void build_kernel(const float* __restrict__ P, const float* __restrict__ A) {
    const int row = blockIdx.x, t = threadIdx.x;
    __shared__ unsigned long long keys[KF];
    __shared__ float a2s[KF];
    __shared__ int flg[KF];

    const float a = A[(size_t)row * KF + t];
    const float p = P[(size_t)row * KF + t];
    unsigned long long key =
        ((unsigned long long)__float_as_uint(a) << 32) | (unsigned)(0xFFFFFFFFu - t);
    keys[t] = key;
    __syncthreads();
    int rank = 0;
#pragma unroll 8
    for (int i = 0; i < KF; i++) rank += (keys[i] > key);
    const bool sel = rank < CT;

    float c = 0.f, s = 0.f;
    if (sel) { c = __fmul_rn(a, cosf(p)); s = __fmul_rn(a, sinf(p)); }
    g_T[(size_t)t * NN + row] = make_float2(c, s);

    a2s[t] = sel ? __fmul_rn(a, a) : 0.f;
    flg[t] = sel ? 1 : 0;
    __syncthreads();
    if (t < 32) {   // emulate f32 warp row-reduce: strided serial 8 + shfl tree
        float acc = 0.f;
#pragma unroll
        for (int i = 0; i < 8; i++) acc = __fadd_rn(acc, a2s[t + 32 * i]);
#pragma unroll
        for (int d = 16; d; d >>= 1)
            acc = __fadd_rn(acc, __shfl_down_sync(0xffffffffu, acc, d));
        if (t == 0) g_sqf[row] = acc;
    }
    if (sel) {
        int pos = 0;
        for (int i = 0; i < t; i++) pos += flg[i];
        g_kk8[(size_t)row * CT + pos] = (uint8_t)t;
        g_csr[(size_t)row * CT + pos] = make_float2(c, s);
    }
    if (t == 0) {
        int j0 = 0;
        for (int i = 0; i < 128; i++) j0 += flg[i];
        g_j0[row] = (uint8_t)j0;
    }
}

// ---------------- entry kernel: bit-exact serial-k fp32 R entries --------------
// Block = 64n x 64m, 8 warps (8 n each, 2 m per lane). K in two 128-k stages
// sharing one 64KB tile buffer; serial ascending-k FMA order preserved across
// stages (bit-identical to dense serial-k; skipped zero-k terms are exact
// no-ops). Upper blocks only (mB >= nB); result staged in smem and written to
// both (n,m) and transposed (m,n) — bitwise equal by FP commutativity.
#define SM_TILE 0                           // float4[128][32]  64 KB
#define SM_CS   (128 * 32 * 16)             // float2[64][32]   16 KB
#define SM_KK   (SM_CS + 64 * 32 * 8)       // u8[64][32]        2 KB
#define SM_J0   (SM_KK + 64 * 32)           // u8[64]
#define SM_OUT  (SM_J0 + 64)                // float[64][68]  17.4 KB
#define SM_TOT  (SM_OUT + 64 * 68 * 4)      // 101440 B -> 2 CTAs/SM

__global__ void __launch_bounds__(256, 2) entry_kernel(float* __restrict__ out) {
    const int mB = blockIdx.x * 64, nB = blockIdx.y * 64;
    if (mB < nB) return;
    extern __shared__ char smem[];
    float4* tile = (float4*)(smem + SM_TILE);   // [k'][m-pair] (c0,s0,c1,s1)
    float2* cs  = (float2*)(smem + SM_CS);      // [nl][j]
    uint8_t* kk = (uint8_t*)(smem + SM_KK);
    uint8_t* j0s = (uint8_t*)(smem + SM_J0);
    float*  sout = (float*)(smem + SM_OUT);     // [m'][68] staging

    const int t = threadIdx.x, w = t >> 5, lane = t & 31;

    // CSR for 64 n rows
    for (int idx = t; idx < 64 * 32; idx += 256) {
        kk[idx] = g_kk8[(size_t)nB * CT + idx];
        cs[idx] = g_csr[(size_t)nB * CT + idx];
    }
    if (t < 64) j0s[t] = g_j0[nB + t];
    // stage 0 tile: k in [0,128)
    for (int idx = t; idx < 128 * 32; idx += 256) {
        const int k = idx >> 5, pr = idx & 5 * 6 + 1;  // (idx & 31)
        const int prr = idx & 31;
        tile[idx] = *(const float4*)(g_T + (size_t)k * NN + mB + 2 * prr);
        (void)pr;
    }
    __syncthreads();

    float4 acc[8];
#pragma unroll
    for (int i = 0; i < 8; i++) acc[i] = make_float4(0.f, 0.f, 0.f, 0.f);

#pragma unroll 1
    for (int jj = 0; jj < 8; jj++) {
        const int nl = w * 8 + jj;
        const int jend = j0s[nl];
        float4 a = acc[jj];
#pragma unroll 1
        for (int j = 0; j < jend; j++) {
            const int k = kk[nl * 32 + j];
            const float2 v = cs[nl * 32 + j];
            const float4 tv = tile[k * 32 + lane];
            a.x = __fmaf_rn(v.x, tv.x, a.x);   // c*c  (m0)
            a.y = __fmaf_rn(v.y, tv.y, a.y);   // s*s  (m0)
            a.z = __fmaf_rn(v.x, tv.z, a.z);   // c*c  (m1)
            a.w = __fmaf_rn(v.y, tv.w, a.w);   // s*s  (m1)
        }
        acc[jj] = a;
    }
    __syncthreads();
    // stage 1 tile: k in [128,256)
    for (int idx = t; idx < 128 * 32; idx += 256) {
        const int k = idx >> 5, prr = idx & 31;
        tile[idx] = *(const float4*)(g_T + (size_t)(k + 128) * NN + mB + 2 * prr);
    }
    __syncthreads();

#pragma unroll 1
    for (int jj = 0; jj < 8; jj++) {
        const int nl = w * 8 + jj;
        const int jbeg = j0s[nl];
        float4 a = acc[jj];
#pragma unroll 1
        for (int j = jbeg; j < 32; j++) {
            const int k = kk[nl * 32 + j] - 128;
            const float2 v = cs[nl * 32 + j];
            const float4 tv = tile[k * 32 + lane];
            a.x = __fmaf_rn(v.x, tv.x, a.x);
            a.y = __fmaf_rn(v.y, tv.y, a.y);
            a.z = __fmaf_rn(v.x, tv.z, a.z);
            a.w = __fmaf_rn(v.y, tv.w, a.w);
        }
        acc[jj] = a;
    }

    // epilogue: same fp recipe as R14 (bitwise): num=fadd(ac,as); den=sqrt(add(mul,eps))
    const float2 sqm = *(const float2*)(g_sqf + mB + 2 * lane);
#pragma unroll
    for (int jj = 0; jj < 8; jj++) {
        const int nl = w * 8 + jj;
        const float sqn = g_sqf[nB + nl];
        float2 r;
        r.x = __fdiv_rn(__fadd_rn(acc[jj].x, acc[jj].y),
                        __fsqrt_rn(__fadd_rn(__fmul_rn(sqn, sqm.x), EPSF)));
        r.y = __fdiv_rn(__fadd_rn(acc[jj].z, acc[jj].w),
                        __fsqrt_rn(__fadd_rn(__fmul_rn(sqn, sqm.y), EPSF)));
        *(float2*)(out + (size_t)(nB + nl) * NN + mB + 2 * lane) = r;
        sout[(2 * lane)     * 68 + nl] = r.x;
        sout[(2 * lane + 1) * 68 + nl] = r.y;
    }

    // transposed block write (strictly-lower mirror), bitwise-equal values
    if (mB != nB) {
        __syncthreads();
        for (int idx = t; idx < 64 * 16; idx += 256) {
            const int mr = idx >> 4, q = idx & 15;
            const float4 v = *(const float4*)(sout + mr * 68 + 4 * q);
            *(float4*)(out + (size_t)(mB + mr) * NN + nB + 4 * q) = v;
        }
    }
}

// ---------------- fused rowsum + stats (one pass over R) -----------------------
// Rowsum reduce order byte-identical to R14 (den bits unchanged).
__global__ void __launch_bounds__(1024) rowsum_stats_kernel(const float* __restrict__ R) {
    const int n = blockIdx.x, t = threadIdx.x;
    const float2* r2 = (const float2*)(R + (size_t)n * NN);
    __shared__ float sp[32];
    __shared__ float sden, srcp;
    __shared__ double dsp[32];
    __shared__ unsigned int csp[32];

    float2 v[4];
    float acc = 0.f;
#pragma unroll
    for (int i = 0; i < 4; i++) {
        v[i] = r2[t + 1024 * i];
        acc = __fadd_rn(acc, v[i].x);
        acc = __fadd_rn(acc, v[i].y);
    }
#pragma unroll
    for (int d = 16; d; d >>= 1)
        acc = __fadd_rn(acc, __shfl_down_sync(0xffffffffu, acc, d));
    if ((t & 31) == 0) sp[t >> 5] = acc;
    __syncthreads();
    if (t < 32) {
        float a = sp[t];
#pragma unroll
        for (int d = 16; d; d >>= 1)
            a = __fadd_rn(a, __shfl_down_sync(0xffffffffu, a, d));
        if (t == 0) {
            const float den = __fadd_rn(a, EPSF);
            g_den[n] = den; sden = den;
            const float y = __fdiv_rn(1.0f, den);
            g_rcp[n] = y; srcp = y;
        }
    }
    __syncthreads();

    const float den = sden, y = srcp;
    double ps = 0.0; unsigned int pc = 0;
#pragma unroll
    for (int i = 0; i < 4; i++) {
        float rp;
        rp = mdiv(v[i].x, den, y); if (rp > 0.f) { ps += (double)rp; pc++; }
        rp = mdiv(v[i].y, den, y); if (rp > 0.f) { ps += (double)rp; pc++; }
    }
#pragma unroll
    for (int d = 16; d; d >>= 1) {
        ps += __shfl_down_sync(0xffffffffu, ps, d);
        pc += __shfl_down_sync(0xffffffffu, pc, d);
    }
    if ((t & 31) == 0) { dsp[t >> 5] = ps; csp[t >> 5] = pc; }
    __syncthreads();
    if (t < 32) {
        double a = dsp[t]; unsigned int c = csp[t];
#pragma unroll
        for (int d = 16; d; d >>= 1) {
            a += __shfl_down_sync(0xffffffffu, a, d);
            c += __shfl_down_sync(0xffffffffu, c, d);
        }
        if (t == 0) {
            atomicAdd(&g_psum, a);
            atomicAdd(&g_pcnt, (unsigned long long)c);
        }
    }
}

__global__ void tau_kernel() {
    double cnt = (double)g_pcnt;
    if (cnt < 1.0) cnt = 1.0;
    const double mp = g_psum / cnt;
    g_tau = (mp > 0.0) ? (float)mp : 1.0f;
}

// ---------------- threshold: R_hat = where(R' >= tau, R', 0) -------------------
__global__ void thresh_kernel(float* __restrict__ R) {
    const int i = blockIdx.x * blockDim.x + threadIdx.x;  // float4 index
    float4* R4 = (float4*)R;
    float4 v = R4[i];
    const int row = i >> 11;                               // 2048 float4 per row
    const float den = g_den[row];
    const float y = g_rcp[row];
    const float tau = g_tau;
    float x;
    x = mdiv(v.x, den, y); v.x = (x >= tau) ? x : 0.f;
    x = mdiv(v.y, den, y); v.y = (x >= tau) ? x : 0.f;
    x = mdiv(v.z, den, y); v.z = (x >= tau) ? x : 0.f;
    x = mdiv(v.w, den, y); v.w = (x >= tau) ? x : 0.f;
    R4[i] = v;
}

// ---------------- launch ----------------
extern "C" void kernel_launch(void* const* d_in, const int* in_sizes, int n_in,
                              void* d_out, int out_size) {
    const float* P = (const float*)d_in[0];
    const float* A = (const float*)d_in[1];
    float* out = (float*)d_out;

    cudaFuncSetAttribute(entry_kernel,
                         cudaFuncAttributeMaxDynamicSharedMemorySize, SM_TOT);

    zero_stats_kernel<<<1, 1>>>();
    build_kernel<<<NN, 256>>>(P, A);
    entry_kernel<<<dim3(NN / 64, NN / 64), 256, SM_TOT>>>(out);
    rowsum_stats_kernel<<<NN, 1024>>>(out);
    tau_kernel<<<1, 1>>>();
    thresh_kernel<<<(NN / 4) * (NN / 256), 256>>>(out);
}